// round 11
// baseline (speedup 1.0000x reference)
#include <cuda_runtime.h>

// ConstrainLoss: spatial-softmax moment loss.
// x: (B=256, 13, 13, C=1024) fp32. Output: scalar fp32.
//
// Per (b,h,w): f = softmax_c(x). Per (b,c): S0,S1x,S2x,S1y,S2y over 169 positions.
// var_x = (S2x - 2 mx S1x + mx^2 S0) / (169 (S0+eps)), mx = S1x/(S0+eps); same y.
// det = (vx+vy)^2 * Z ; out = sum over (b,c) / (B*C).
//
// Single fused kernel: one block per batch element computes all moments in
// registers, reduces det over channels, then the LAST block (threadfence
// reduction) folds the 256 per-batch partials into the scalar output.
// Total HBM traffic = the input, once.

#define CCH  1024
#define HWD  13
#define BMAX 256
#define TPB  512      // 512 threads, thread t owns channels (2t, 2t+1)

__device__ float g_partial[BMAX];
__device__ int   g_count;          // zero-init at load; reset by last block

__device__ __forceinline__ float warp_sum(float v) {
    v += __shfl_xor_sync(0xffffffffu, v, 16);
    v += __shfl_xor_sync(0xffffffffu, v, 8);
    v += __shfl_xor_sync(0xffffffffu, v, 4);
    v += __shfl_xor_sync(0xffffffffu, v, 2);
    v += __shfl_xor_sync(0xffffffffu, v, 1);
    return v;
}

// ---------------------------------------------------------------------------
// grid = B (256); block = 512, occ 2 -> all blocks co-resident (one wave).
// Per row: 13 coalesced LDG.64 -> exp -> staged two-level softmax-sum
// (fold-by-2 shuffle + half-warp STS; 13 warps finish via 2x LDS.128 +
//  one butterfly) -> register moment accumulation. 2 barriers per row.
// ---------------------------------------------------------------------------
__global__ __launch_bounds__(TPB, 2)
void fused_kernel(const float* __restrict__ x, float* __restrict__ out, int B) {
    const int b    = blockIdx.x;
    const int t    = threadIdx.x;
    const int warp = t >> 5;
    const int lane = t & 31;

    __shared__ float se[HWD][256];   // per-position staged partials (4-ch sums)
    __shared__ float s_inv[HWD];     // per-position 1/sum(exp)

    float2 s0  = {0.f, 0.f}, s1x = {0.f, 0.f}, s2x = {0.f, 0.f};
    float2 s1y = {0.f, 0.f}, s2y = {0.f, 0.f};

    for (int h = 0; h < HWD; ++h) {
        const float2* p =
            (const float2*)(x + (((size_t)b * HWD + h) * HWD) * CCH) + t;

        // 13 independent coalesced LDG.64 -> exp (no max-subtract: |x| < ~6)
        float2 e[HWD];
#pragma unroll
        for (int w = 0; w < HWD; ++w) {
            float2 v = __ldg(p + (size_t)w * (CCH / 2));
            e[w].x = __expf(v.x);
            e[w].y = __expf(v.y);
        }

        // Phase 1: thread-pair fold + half-warp store (16 partials per warp)
#pragma unroll
        for (int w = 0; w < HWD; ++w) {
            float v = e[w].x + e[w].y;
            v += __shfl_xor_sync(0xffffffffu, v, 16);
            if (lane < 16) se[w][(warp << 4) + lane] = v;
        }
        __syncthreads();

        // Phase 2: warps 0..12 each finish one position (256 partials)
        if (warp < HWD) {
            const float4* q = (const float4*)se[warp];
            float4 a  = q[lane];
            float4 bq = q[lane + 32];
            float v = ((a.x + a.y) + (a.z + a.w)) +
                      ((bq.x + bq.y) + (bq.z + bq.w));
            v = warp_sum(v);
            if (lane == 0) s_inv[warp] = __frcp_rn(v);
        }
        __syncthreads();

        // Phase 3: accumulate moments. yv = w+1 compile-time immediates,
        // xv row-constant -> folded out of the inner loop.
        float2 r0 = {0.f, 0.f}, r1y = {0.f, 0.f}, r2y = {0.f, 0.f};
#pragma unroll
        for (int w = 0; w < HWD; ++w) {
            const float inv = s_inv[w];
            const float yv  = (float)(w + 1);
            const float gx  = e[w].x * inv;
            const float gy  = e[w].y * inv;
            r0.x += gx;                       r0.y += gy;
            r1y.x = fmaf(yv, gx, r1y.x);      r1y.y = fmaf(yv, gy, r1y.y);
            r2y.x = fmaf(yv * yv, gx, r2y.x); r2y.y = fmaf(yv * yv, gy, r2y.y);
        }
        const float xv = (float)(h + 1);
        s0.x  += r0.x;                        s0.y  += r0.y;
        s1x.x  = fmaf(xv, r0.x, s1x.x);       s1x.y  = fmaf(xv, r0.y, s1x.y);
        s2x.x  = fmaf(xv * xv, r0.x, s2x.x);  s2x.y  = fmaf(xv * xv, r0.y, s2x.y);
        s1y.x += r1y.x;                       s1y.y += r1y.y;
        s2y.x += r2y.x;                       s2y.y += r2y.y;
        // se/s_inv reuse is safe: phase-2 reads complete before the second
        // barrier; next row's writes come after it. s_inv reads (phase 3)
        // complete before the next row's first barrier.
    }

    // ---- Epilogue: det per channel, reduce over the block ----
    const float Z = 17.079468445347132f;   // exp(log(2*pi) + 1) = 2*pi*e
    float dsum;
    {
        // channel .x
        float s      = s0.x + 1e-6f;
        float inv_s  = 1.0f / s;
        float mx     = s1x.x * inv_s;
        float my     = s1y.x * inv_s;
        float inv169 = inv_s * (1.0f / 169.0f);
        float vx = (s2x.x - 2.0f * mx * s1x.x + mx * mx * s0.x) * inv169;
        float vy = (s2y.x - 2.0f * my * s1y.x + my * my * s0.x) * inv169;
        float tt = vx + vy;
        dsum = tt * tt * Z;
    }
    {
        // channel .y
        float s      = s0.y + 1e-6f;
        float inv_s  = 1.0f / s;
        float mx     = s1x.y * inv_s;
        float my     = s1y.y * inv_s;
        float inv169 = inv_s * (1.0f / 169.0f);
        float vx = (s2x.y - 2.0f * mx * s1x.y + mx * mx * s0.y) * inv169;
        float vy = (s2y.y - 2.0f * my * s1y.y + my * my * s0.y) * inv169;
        float tt = vx + vy;
        dsum += tt * tt * Z;
    }

    __shared__ float rs[16];
    float v = warp_sum(dsum);
    if (lane == 0) rs[warp] = v;
    __syncthreads();
    if (t == 0) {
        float u = 0.f;
#pragma unroll
        for (int i = 0; i < 16; ++i) u += rs[i];
        g_partial[b] = u;
    }

    // ---- Last-block final reduction (threadfence-reduction pattern) ----
    __shared__ int is_last;
    __threadfence();                     // flush g_partial[b] before counting
    if (t == 0) {
        int cnt = atomicAdd(&g_count, 1);
        is_last = (cnt == gridDim.x - 1);
    }
    __syncthreads();

    if (is_last) {
        // Deterministic: exactly one block executes this, reading all
        // partials in fixed index order -> bitwise-stable result.
        float pv = (t < B) ? g_partial[t] : 0.f;   // B <= 256 < TPB
        pv = warp_sum(pv);
        if (lane == 0) rs[warp] = pv;
        __syncthreads();
        if (warp == 0) {
            float u = (lane < 16) ? rs[lane] : 0.f;
            u = warp_sum(u);
            if (lane == 0) {
                out[0] = u / ((float)B * (float)CCH);
                g_count = 0;             // reset for next graph replay
            }
        }
    }
}

// ---------------------------------------------------------------------------
extern "C" void kernel_launch(void* const* d_in, const int* in_sizes, int n_in,
                              void* d_out, int out_size) {
    const float* x = (const float*)d_in[0];
    int B = in_sizes[0] / (HWD * HWD * CCH);   // 256
    if (B > BMAX) B = BMAX;

    fused_kernel<<<B, TPB>>>(x, (float*)d_out, B);
}

// round 12
// speedup vs baseline: 1.0706x; 1.0706x over previous
#include <cuda_runtime.h>

// ConstrainLoss: spatial-softmax moment loss.
// x: (B=256, 13, 13, C=1024) fp32. Output: scalar fp32.
//
// Per (b,h,w): f = softmax_c(x). Per (b,c): S0,S1x,S2x,S1y,S2y over 169 positions.
// var_x = (S2x - 2 mx S1x + mx^2 S0) / (169 (S0+eps)), mx = S1x/(S0+eps); same y.
// det = (vx+vy)^2 * Z ; out = sum over (b,c) / (B*C).
//
// Single fused kernel: one block per batch element computes all moments in
// registers, reduces det over channels -> g_partial[b]. Completion tracked by
// HIERARCHICAL counters (16 L2-line-spread group counters + 1 root) so the
// one-wave simultaneous finish does NOT serialize ~256 atomics on one address
// (that serialization cost ~4us in R10). The last block's warp 0 folds the
// 256 partials (fixed order -> deterministic) and resets counters for replay.

#define CCH  1024
#define HWD  13
#define BMAX 256
#define TPB  512      // 512 threads, thread t owns channels (2t, 2t+1)
#define NGRP 16
#define GPAD 32       // 32 ints = 128B stride -> distinct L2 lines per counter

__device__ float g_partial[BMAX];
__device__ int   g_cnt1[NGRP * GPAD];   // zero-init; reset by last block
__device__ int   g_cnt2;                // zero-init; reset by last block

__device__ __forceinline__ float warp_sum(float v) {
    v += __shfl_xor_sync(0xffffffffu, v, 16);
    v += __shfl_xor_sync(0xffffffffu, v, 8);
    v += __shfl_xor_sync(0xffffffffu, v, 4);
    v += __shfl_xor_sync(0xffffffffu, v, 2);
    v += __shfl_xor_sync(0xffffffffu, v, 1);
    return v;
}

// ---------------------------------------------------------------------------
// grid = B (256); block = 512, occ 2 -> all blocks co-resident (one wave).
// Per row: 13 coalesced LDG.64 -> exp -> staged two-level softmax-sum
// (fold-by-2 shuffle + half-warp STS; 13 warps finish via 2x LDS.128 +
//  one butterfly) -> register moment accumulation. 2 barriers per row.
// ---------------------------------------------------------------------------
__global__ __launch_bounds__(TPB, 2)
void fused_kernel(const float* __restrict__ x, float* __restrict__ out, int B) {
    const int b    = blockIdx.x;
    const int t    = threadIdx.x;
    const int warp = t >> 5;
    const int lane = t & 31;

    __shared__ float se[HWD][256];   // per-position staged partials (4-ch sums)
    __shared__ float s_inv[HWD];     // per-position 1/sum(exp)

    float2 s0  = {0.f, 0.f}, s1x = {0.f, 0.f}, s2x = {0.f, 0.f};
    float2 s1y = {0.f, 0.f}, s2y = {0.f, 0.f};

    for (int h = 0; h < HWD; ++h) {
        const float2* p =
            (const float2*)(x + (((size_t)b * HWD + h) * HWD) * CCH) + t;

        // 13 independent coalesced LDG.64 -> exp (no max-subtract: |x| < ~6)
        float2 e[HWD];
#pragma unroll
        for (int w = 0; w < HWD; ++w) {
            float2 v = __ldg(p + (size_t)w * (CCH / 2));
            e[w].x = __expf(v.x);
            e[w].y = __expf(v.y);
        }

        // Phase 1: thread-pair fold + half-warp store (16 partials per warp)
#pragma unroll
        for (int w = 0; w < HWD; ++w) {
            float v = e[w].x + e[w].y;
            v += __shfl_xor_sync(0xffffffffu, v, 16);
            if (lane < 16) se[w][(warp << 4) + lane] = v;
        }
        __syncthreads();

        // Phase 2: warps 0..12 each finish one position (256 partials)
        if (warp < HWD) {
            const float4* q = (const float4*)se[warp];
            float4 a  = q[lane];
            float4 bq = q[lane + 32];
            float v = ((a.x + a.y) + (a.z + a.w)) +
                      ((bq.x + bq.y) + (bq.z + bq.w));
            v = warp_sum(v);
            if (lane == 0) s_inv[warp] = __frcp_rn(v);
        }
        __syncthreads();

        // Phase 3: accumulate moments. yv = w+1 compile-time immediates,
        // xv row-constant -> folded out of the inner loop.
        float2 r0 = {0.f, 0.f}, r1y = {0.f, 0.f}, r2y = {0.f, 0.f};
#pragma unroll
        for (int w = 0; w < HWD; ++w) {
            const float inv = s_inv[w];
            const float yv  = (float)(w + 1);
            const float gx  = e[w].x * inv;
            const float gy  = e[w].y * inv;
            r0.x += gx;                       r0.y += gy;
            r1y.x = fmaf(yv, gx, r1y.x);      r1y.y = fmaf(yv, gy, r1y.y);
            r2y.x = fmaf(yv * yv, gx, r2y.x); r2y.y = fmaf(yv * yv, gy, r2y.y);
        }
        const float xv = (float)(h + 1);
        s0.x  += r0.x;                        s0.y  += r0.y;
        s1x.x  = fmaf(xv, r0.x, s1x.x);       s1x.y  = fmaf(xv, r0.y, s1x.y);
        s2x.x  = fmaf(xv * xv, r0.x, s2x.x);  s2x.y  = fmaf(xv * xv, r0.y, s2x.y);
        s1y.x += r1y.x;                       s1y.y += r1y.y;
        s2y.x += r2y.x;                       s2y.y += r2y.y;
        // se/s_inv reuse is safe: phase-2 reads complete before the second
        // barrier; next row's writes come after it. s_inv reads (phase 3)
        // complete before the next row's first barrier.
    }

    // ---- Epilogue: det per channel, reduce over the block ----
    const float Z = 17.079468445347132f;   // exp(log(2*pi) + 1) = 2*pi*e
    float dsum;
    {
        // channel .x
        float s      = s0.x + 1e-6f;
        float inv_s  = 1.0f / s;
        float mx     = s1x.x * inv_s;
        float my     = s1y.x * inv_s;
        float inv169 = inv_s * (1.0f / 169.0f);
        float vx = (s2x.x - 2.0f * mx * s1x.x + mx * mx * s0.x) * inv169;
        float vy = (s2y.x - 2.0f * my * s1y.x + my * my * s0.x) * inv169;
        float tt = vx + vy;
        dsum = tt * tt * Z;
    }
    {
        // channel .y
        float s      = s0.y + 1e-6f;
        float inv_s  = 1.0f / s;
        float mx     = s1x.y * inv_s;
        float my     = s1y.y * inv_s;
        float inv169 = inv_s * (1.0f / 169.0f);
        float vx = (s2x.y - 2.0f * mx * s1x.y + mx * mx * s0.y) * inv169;
        float vy = (s2y.y - 2.0f * my * s1y.y + my * my * s0.y) * inv169;
        float tt = vx + vy;
        dsum += tt * tt * Z;
    }

    __shared__ float rs[16];
    float v = warp_sum(dsum);
    if (lane == 0) rs[warp] = v;
    __syncthreads();
    // Warps 1..15 are done after this barrier and exit; only warp 0 runs the
    // completion protocol -> no extra block-wide syncs, no smem broadcast.
    if (warp != 0) return;

    float u = (lane < 16) ? rs[lane] : 0.f;
    u = warp_sum(u);

    int last = 0;
    if (lane == 0) {
        g_partial[b] = u;
        __threadfence();                 // publish partial before counting
        // Level 1: 16 counters, 128B apart; b&15 spreads simultaneous
        // finishers across distinct L2 lines (~16 serialized ops each).
        const int grp = b & (NGRP - 1);
        const int per_grp = B >> 4;      // 16 when B==256
        if (atomicAdd(&g_cnt1[grp * GPAD], 1) == per_grp - 1) {
            // Level 2: at most 16 ops on one address.
            if (atomicAdd(&g_cnt2, 1) == NGRP - 1) last = 1;
        }
    }
    last = __shfl_sync(0xffffffffu, last, 0);

    if (last) {
        __threadfence();                 // order counter wins before reads
        // Deterministic: exactly one warp executes this, fixed per-lane
        // accumulation order -> bitwise-stable across replays.
        float pv = 0.f;
#pragma unroll
        for (int i = 0; i < BMAX; i += 32)
            if (i + lane < B) pv += g_partial[i + lane];
        pv = warp_sum(pv);
        if (lane == 0) {
            out[0] = pv / ((float)B * (float)CCH);
            // Reset counters for the next graph replay (kernel-completion
            // ordering makes these visible before the next launch's atomics).
#pragma unroll
            for (int gidx = 0; gidx < NGRP; ++gidx) g_cnt1[gidx * GPAD] = 0;
            g_cnt2 = 0;
        }
    }
}

// ---------------------------------------------------------------------------
extern "C" void kernel_launch(void* const* d_in, const int* in_sizes, int n_in,
                              void* d_out, int out_size) {
    const float* x = (const float*)d_in[0];
    int B = in_sizes[0] / (HWD * HWD * CCH);   // 256
    if (B > BMAX) B = BMAX;

    fused_kernel<<<B, TPB>>>(x, (float*)d_out, B);
}

// round 13
// speedup vs baseline: 1.1323x; 1.0576x over previous
#include <cuda_runtime.h>

// ConstrainLoss: spatial-softmax moment loss.
// x: (B=256, 13, 13, C=1024) fp32. Output: scalar fp32.
//
// Per (b,h,w): f = softmax_c(x). Per (b,c): S0,S1x,S2x,S1y,S2y over 169 positions.
// var_x = (S2x - 2 mx S1x + mx^2 S0) / (169 (S0+eps)), mx = S1x/(S0+eps); same y.
// det = (vx+vy)^2 * Z ; out = sum over (b,c) / (B*C).
//
// Structure: tiny zero_out kernel (clears the scalar), then one fused kernel
// (one block per batch element, moments in registers, det + block reduction),
// each block RED.ADDs its pre-scaled partial into out[0]. Fire-and-forget:
// no fences, no completion counters, no last-block serialization.

#define CCH  1024
#define HWD  13
#define BMAX 256
#define TPB  512      // 512 threads, thread t owns channels (2t, 2t+1)

__device__ __forceinline__ float warp_sum(float v) {
    v += __shfl_xor_sync(0xffffffffu, v, 16);
    v += __shfl_xor_sync(0xffffffffu, v, 8);
    v += __shfl_xor_sync(0xffffffffu, v, 4);
    v += __shfl_xor_sync(0xffffffffu, v, 2);
    v += __shfl_xor_sync(0xffffffffu, v, 1);
    return v;
}

// ---------------------------------------------------------------------------
// Kernel 0: clear the output scalar (d_out is poisoned to 0xAA by harness).
// ---------------------------------------------------------------------------
__global__ void zero_out(float* __restrict__ out) { out[0] = 0.0f; }

// ---------------------------------------------------------------------------
// Kernel 1: fused per-batch moments + det + channel reduction + RED to out.
// grid = B (256); block = 512, occ 2.
// Per row: 13 coalesced LDG.64 -> exp -> staged two-level softmax-sum
// (fold-by-2 shuffle + half-warp STS; 13 warps finish via 2x LDS.128 +
//  one butterfly) -> register moment accumulation. 2 barriers per row.
// ---------------------------------------------------------------------------
__global__ __launch_bounds__(TPB, 2)
void fused_kernel(const float* __restrict__ x, float* __restrict__ out,
                  float inv_bc) {
    const int b    = blockIdx.x;
    const int t    = threadIdx.x;
    const int warp = t >> 5;
    const int lane = t & 31;

    __shared__ float se[HWD][256];   // per-position staged partials (4-ch sums)
    __shared__ float s_inv[HWD];     // per-position 1/sum(exp)

    float2 s0  = {0.f, 0.f}, s1x = {0.f, 0.f}, s2x = {0.f, 0.f};
    float2 s1y = {0.f, 0.f}, s2y = {0.f, 0.f};

    for (int h = 0; h < HWD; ++h) {
        const float2* p =
            (const float2*)(x + (((size_t)b * HWD + h) * HWD) * CCH) + t;

        // 13 independent coalesced LDG.64 -> exp (no max-subtract: |x| < ~6)
        float2 e[HWD];
#pragma unroll
        for (int w = 0; w < HWD; ++w) {
            float2 v = __ldg(p + (size_t)w * (CCH / 2));
            e[w].x = __expf(v.x);
            e[w].y = __expf(v.y);
        }

        // Phase 1: thread-pair fold + half-warp store (16 partials per warp)
#pragma unroll
        for (int w = 0; w < HWD; ++w) {
            float v = e[w].x + e[w].y;
            v += __shfl_xor_sync(0xffffffffu, v, 16);
            if (lane < 16) se[w][(warp << 4) + lane] = v;
        }
        __syncthreads();

        // Phase 2: warps 0..12 each finish one position (256 partials)
        if (warp < HWD) {
            const float4* q = (const float4*)se[warp];
            float4 a  = q[lane];
            float4 bq = q[lane + 32];
            float v = ((a.x + a.y) + (a.z + a.w)) +
                      ((bq.x + bq.y) + (bq.z + bq.w));
            v = warp_sum(v);
            if (lane == 0) s_inv[warp] = __frcp_rn(v);
        }
        __syncthreads();

        // Phase 3: accumulate moments. yv = w+1 compile-time immediates,
        // xv row-constant -> folded out of the inner loop.
        float2 r0 = {0.f, 0.f}, r1y = {0.f, 0.f}, r2y = {0.f, 0.f};
#pragma unroll
        for (int w = 0; w < HWD; ++w) {
            const float inv = s_inv[w];
            const float yv  = (float)(w + 1);
            const float gx  = e[w].x * inv;
            const float gy  = e[w].y * inv;
            r0.x += gx;                       r0.y += gy;
            r1y.x = fmaf(yv, gx, r1y.x);      r1y.y = fmaf(yv, gy, r1y.y);
            r2y.x = fmaf(yv * yv, gx, r2y.x); r2y.y = fmaf(yv * yv, gy, r2y.y);
        }
        const float xv = (float)(h + 1);
        s0.x  += r0.x;                        s0.y  += r0.y;
        s1x.x  = fmaf(xv, r0.x, s1x.x);       s1x.y  = fmaf(xv, r0.y, s1x.y);
        s2x.x  = fmaf(xv * xv, r0.x, s2x.x);  s2x.y  = fmaf(xv * xv, r0.y, s2x.y);
        s1y.x += r1y.x;                       s1y.y += r1y.y;
        s2y.x += r2y.x;                       s2y.y += r2y.y;
        // se/s_inv reuse is safe: phase-2 reads complete before the second
        // barrier; next row's writes come after it. s_inv reads (phase 3)
        // complete before the next row's first barrier.
    }

    // ---- Epilogue: det per channel, reduce over the block ----
    const float Z = 17.079468445347132f;   // exp(log(2*pi) + 1) = 2*pi*e
    float dsum;
    {
        // channel .x
        float s      = s0.x + 1e-6f;
        float inv_s  = 1.0f / s;
        float mx     = s1x.x * inv_s;
        float my     = s1y.x * inv_s;
        float inv169 = inv_s * (1.0f / 169.0f);
        float vx = (s2x.x - 2.0f * mx * s1x.x + mx * mx * s0.x) * inv169;
        float vy = (s2y.x - 2.0f * my * s1y.x + my * my * s0.x) * inv169;
        float tt = vx + vy;
        dsum = tt * tt * Z;
    }
    {
        // channel .y
        float s      = s0.y + 1e-6f;
        float inv_s  = 1.0f / s;
        float mx     = s1x.y * inv_s;
        float my     = s1y.y * inv_s;
        float inv169 = inv_s * (1.0f / 169.0f);
        float vx = (s2x.y - 2.0f * mx * s1x.y + mx * mx * s0.y) * inv169;
        float vy = (s2y.y - 2.0f * my * s1y.y + my * my * s0.y) * inv169;
        float tt = vx + vy;
        dsum += tt * tt * Z;
    }

    __shared__ float rs[16];
    float v = warp_sum(dsum);
    if (lane == 0) rs[warp] = v;
    __syncthreads();
    if (warp != 0) return;            // warps 1..15 done

    float u = (lane < 16) ? rs[lane] : 0.f;
    u = warp_sum(u);
    if (lane == 0) {
        // Fire-and-forget accumulation (RED.E.ADD.F32): no fence, no counter,
        // no branch on a returned value. fp32 add is commutative; 256
        // positive contributions -> order jitter ~1e-7 rel, tolerance 1e-3.
        atomicAdd(out, u * inv_bc);
    }
}

// ---------------------------------------------------------------------------
extern "C" void kernel_launch(void* const* d_in, const int* in_sizes, int n_in,
                              void* d_out, int out_size) {
    const float* x = (const float*)d_in[0];
    int B = in_sizes[0] / (HWD * HWD * CCH);   // 256
    if (B > BMAX) B = BMAX;

    float* out = (float*)d_out;
    const float inv_bc = 1.0f / ((float)B * (float)CCH);

    zero_out<<<1, 1>>>(out);
    fused_kernel<<<B, TPB>>>(x, out, inv_bc);
}